// round 6
// baseline (speedup 1.0000x reference)
#include <cuda_runtime.h>
#include <cuda_bf16.h>

// Problem constants (fixed shapes from reference)
#define BATCH 8
#define CCH   64
#define DD    32
#define HH    64
#define WW    64
#define S_SPATIAL (DD*HH*WW)       // 131072 spatial positions per (b,c)
#define S4        (S_SPATIAL/4)    // 32768 float4 positions

// 8 MB scratch for reduced tensor [B, 2, D, H, W]
__device__ float g_scratch[BATCH * 2 * S_SPATIAL];

// ---------------------------------------------------------------------------
// Kernel 1: channel-wise mean + max over C=64. (unchanged — ~6.2 TB/s)
// ---------------------------------------------------------------------------
__global__ __launch_bounds__(256) void reduce_mean_max_kernel(const float* __restrict__ x) {
    int idx = blockIdx.x * blockDim.x + threadIdx.x;   // over BATCH * S4
    if (idx >= BATCH * S4) return;
    int b  = idx >> 15;
    int s4 = idx & (S4 - 1);

    const float4* base = reinterpret_cast<const float4*>(x)
                         + (size_t)b * CCH * S4 + s4;

    float4 v = base[0];
    float4 sum = v;
    float4 mx  = v;
    #pragma unroll 8
    for (int c = 1; c < CCH; c++) {
        float4 t = base[(size_t)c * S4];
        sum.x += t.x; sum.y += t.y; sum.z += t.z; sum.w += t.w;
        mx.x = fmaxf(mx.x, t.x); mx.y = fmaxf(mx.y, t.y);
        mx.z = fmaxf(mx.z, t.z); mx.w = fmaxf(mx.w, t.w);
    }
    const float inv = 1.0f / (float)CCH;
    float4 avg = make_float4(sum.x * inv, sum.y * inv, sum.z * inv, sum.w * inv);

    float4* out_avg = reinterpret_cast<float4*>(g_scratch)
                      + (size_t)b * 2 * S4 + s4;
    float4* out_max = out_avg + S4;
    *out_avg = avg;
    *out_max = mx;
}

// ---------------------------------------------------------------------------
// Kernel 2: smem-tiled 3x3x3 SAME conv (2ch -> 1ch) + sigmoid.
// Block (128 thr) tile: 2d x 16h x 64w.  Thread: 8w x 2h outputs.
// Smem tile [2][4][18][64] with pre-zeroed z/y halos.
// Per (ci,dz,row): 2x LDS.128 + 2 width-8 shuffles serve up to 2 oh outputs
// (interior w-halo from registers).  Weights kept in 27 regs per ci phase.
// ---------------------------------------------------------------------------
#define TZ2 4            // 2 d + 2 halo
#define TY2 18           // 16 h + 2 halo
#define TILE_F4 (2*TZ2*TY2*16)     // 2304 float4

__global__ __launch_bounds__(128) void conv_sigmoid_kernel(const float* __restrict__ Wp,
                                                           float* __restrict__ out) {
    __shared__ __align__(16) float sm_in[2][TZ2][TY2][WW];  // 36864 B
    __shared__ float sm_w[56];

    const int tid = threadIdx.x;
    const int bx  = blockIdx.x;            // 512 blocks
    const int ht  = bx & 3;                // 4 h-tiles (16h each)
    const int dt  = (bx >> 2) & 15;        // 16 d-tiles (2d each)
    const int b   = bx >> 6;               // 8 batches
    const int d0  = dt * 2;
    const int h0  = ht * 16;

    // ---- cooperative load: input tile (zero halos) + weights ----
    if (tid < 54) sm_w[tid] = Wp[tid];

    const float* gbase = g_scratch + (size_t)b * 2 * S_SPATIAL;
    #pragma unroll
    for (int i = 0; i < TILE_F4 / 128; i++) {   // 18 iters
        int idx = tid + i * 128;               // 0..2303
        int w16   = idx & 15;
        int rowid = idx >> 4;                  // 0..143
        int y  = rowid % TY2;
        int t2 = rowid / TY2;                  // 0..7
        int z  = t2 & 3;
        int ci = t2 >> 2;
        int gz = d0 + z - 1;
        int gy = h0 + y - 1;
        float4 v = make_float4(0.f, 0.f, 0.f, 0.f);
        if (gz >= 0 && gz < DD && gy >= 0 && gy < HH) {
            v = *reinterpret_cast<const float4*>(gbase + ci * S_SPATIAL
                                                 + (gz * HH + gy) * WW + w16 * 4);
        }
        *reinterpret_cast<float4*>(&sm_in[ci][z][y][w16 * 4]) = v;
    }
    __syncthreads();

    // ---- thread -> (d_local, h-pair, w8) ----
    const int lane  = tid & 31;
    const int lane8 = lane & 7;
    const int w8    = lane8 * 8;
    const int slot  = (tid >> 5) * 4 + (lane >> 3);  // 0..15
    const int dl    = slot & 1;                      // 0..1
    const int h0t   = (slot >> 1) * 2;               // 0,2,..,14 (local h of first output)

    float acc[2][8];
    #pragma unroll
    for (int i = 0; i < 2; i++)
        #pragma unroll
        for (int j = 0; j < 8; j++) acc[i][j] = 0.f;

    #pragma unroll
    for (int ci = 0; ci < 2; ci++) {
        float wreg[27];
        #pragma unroll
        for (int i = 0; i < 27; i++) wreg[i] = sm_w[ci * 27 + i];

        #pragma unroll
        for (int dz = 0; dz < 3; dz++) {
            #pragma unroll
            for (int dyy = 0; dyy < 4; dyy++) {      // smem rows h0t+dyy (halo coords)
                const float* rp = &sm_in[ci][dl + dz][h0t + dyy][w8];
                float4 m0 = *reinterpret_cast<const float4*>(rp);
                float4 m1 = *reinterpret_cast<const float4*>(rp + 4);
                float v0 = __shfl_up_sync(0xffffffffu, m1.w, 1, 8);
                float v9 = __shfl_down_sync(0xffffffffu, m0.x, 1, 8);
                if (lane8 == 0) v0 = 0.f;    // w = -1
                if (lane8 == 7) v9 = 0.f;    // w = 64
                float s0 = v0,   s1 = m0.x, s2 = m0.y, s3 = m0.z, s4 = m0.w;
                float s5 = m1.x, s6 = m1.y, s7 = m1.z, s8 = m1.w, s9 = v9;
                #pragma unroll
                for (int oh = 0; oh < 2; oh++) {
                    const int dy = dyy - oh;          // compile-time
                    if (dy < 0 || dy > 2) continue;   // compile-time prune
                    const float* wr = wreg + dz * 9 + dy * 3;
                    float* a = acc[oh];
                    a[0] = fmaf(s0, wr[0], fmaf(s1, wr[1], fmaf(s2, wr[2], a[0])));
                    a[1] = fmaf(s1, wr[0], fmaf(s2, wr[1], fmaf(s3, wr[2], a[1])));
                    a[2] = fmaf(s2, wr[0], fmaf(s3, wr[1], fmaf(s4, wr[2], a[2])));
                    a[3] = fmaf(s3, wr[0], fmaf(s4, wr[1], fmaf(s5, wr[2], a[3])));
                    a[4] = fmaf(s4, wr[0], fmaf(s5, wr[1], fmaf(s6, wr[2], a[4])));
                    a[5] = fmaf(s5, wr[0], fmaf(s6, wr[1], fmaf(s7, wr[2], a[5])));
                    a[6] = fmaf(s6, wr[0], fmaf(s7, wr[1], fmaf(s8, wr[2], a[6])));
                    a[7] = fmaf(s7, wr[0], fmaf(s8, wr[1], fmaf(s9, wr[2], a[7])));
                }
            }
        }
    }

    #pragma unroll
    for (int oh = 0; oh < 2; oh++) {
        float4 o0, o1;
        o0.x = 1.0f / (1.0f + __expf(-acc[oh][0]));
        o0.y = 1.0f / (1.0f + __expf(-acc[oh][1]));
        o0.z = 1.0f / (1.0f + __expf(-acc[oh][2]));
        o0.w = 1.0f / (1.0f + __expf(-acc[oh][3]));
        o1.x = 1.0f / (1.0f + __expf(-acc[oh][4]));
        o1.y = 1.0f / (1.0f + __expf(-acc[oh][5]));
        o1.z = 1.0f / (1.0f + __expf(-acc[oh][6]));
        o1.w = 1.0f / (1.0f + __expf(-acc[oh][7]));
        float* op = out + (size_t)b * S_SPATIAL
                    + ((d0 + dl) * HH + (h0 + h0t + oh)) * WW + w8;
        *reinterpret_cast<float4*>(op)     = o0;
        *reinterpret_cast<float4*>(op + 4) = o1;
    }
}

extern "C" void kernel_launch(void* const* d_in, const int* in_sizes, int n_in,
                              void* d_out, int out_size) {
    const float* x  = (const float*)d_in[0];   // [8,64,32,64,64]
    const float* Wp = (const float*)d_in[1];   // [1,2,3,3,3] = 54 floats
    float* out = (float*)d_out;                // [8,1,32,64,64]

    {
        int total = BATCH * S4;                // 262144
        int threads = 256;
        int blocks = (total + threads - 1) / threads;
        reduce_mean_max_kernel<<<blocks, threads>>>(x);
    }
    {
        int blocks = BATCH * 16 * 4;           // 512
        conv_sigmoid_kernel<<<blocks, 128>>>(Wp, out);
    }
}